// round 1
// baseline (speedup 1.0000x reference)
#include <cuda_runtime.h>
#include <math.h>

#define BB 2
#define HH 16
#define SS 2048
#define DD 1024
#define DH 64
#define MROWS (BB*SS)   // 4096

static const size_t OUT_ELEMS  = (size_t)BB * SS * DD;            // 4,194,304
static const size_t ATTN_ELEMS = (size_t)BB * HH * SS * SS;       // 134,217,728

// Scratch: __device__ globals (allocation inside kernel_launch is forbidden)
__device__ float g_qp[MROWS * DD];
__device__ float g_kp[MROWS * DD];
__device__ float g_vp[MROWS * DD];
__device__ float g_ctx[MROWS * DD];
// Fallback attn buffer if the harness output only holds `out`
__device__ float g_attn_fb[(size_t)BB * HH * SS * SS];

// ---------------------------------------------------------------------------
// SGEMM with bias: C[M,N] = A[M,K] @ W[K,N] + bias[N]
// A row-major, W row-major. Requires M%128==0, N%128==0, K%8==0.
// 128x128 tile, BK=8, 256 threads, 8x8 per thread.
// ---------------------------------------------------------------------------
__global__ __launch_bounds__(256) void sgemm_bias_kernel(
    const float* __restrict__ A, const float* __restrict__ W,
    const float* __restrict__ bias, float* __restrict__ C,
    int M, int N, int K)
{
    __shared__ float As[8][128];
    __shared__ float Ws[8][128];

    const int tid = threadIdx.x;
    const int tx = tid & 15;        // 0..15 -> col group
    const int ty = tid >> 4;        // 0..15 -> row group
    const int rowBase = blockIdx.y * 128;
    const int colBase = blockIdx.x * 128;

    // A loader: 128 rows x 8 k  -> 256 float4 loads, 1 per thread
    const int aRow = tid >> 1;            // 0..127
    const int aCol = (tid & 1) * 4;       // 0 or 4
    // W loader: 8 rows x 128 cols -> 256 float4 loads, 1 per thread
    const int wRow = tid >> 5;            // 0..7
    const int wCol = (tid & 31) * 4;      // 0..124

    float acc[8][8];
#pragma unroll
    for (int i = 0; i < 8; i++)
#pragma unroll
        for (int j = 0; j < 8; j++) acc[i][j] = 0.f;

    for (int k0 = 0; k0 < K; k0 += 8) {
        float4 av = *(const float4*)(A + (size_t)(rowBase + aRow) * K + k0 + aCol);
        As[aCol + 0][aRow] = av.x;
        As[aCol + 1][aRow] = av.y;
        As[aCol + 2][aRow] = av.z;
        As[aCol + 3][aRow] = av.w;
        float4 wv = *(const float4*)(W + (size_t)(k0 + wRow) * N + colBase + wCol);
        *(float4*)&Ws[wRow][wCol] = wv;
        __syncthreads();
#pragma unroll
        for (int k = 0; k < 8; k++) {
            float4 a0 = *(const float4*)&As[k][ty * 8];
            float4 a1 = *(const float4*)&As[k][ty * 8 + 4];
            float4 b0 = *(const float4*)&Ws[k][tx * 8];
            float4 b1 = *(const float4*)&Ws[k][tx * 8 + 4];
            float ra[8] = {a0.x, a0.y, a0.z, a0.w, a1.x, a1.y, a1.z, a1.w};
            float rb[8] = {b0.x, b0.y, b0.z, b0.w, b1.x, b1.y, b1.z, b1.w};
#pragma unroll
            for (int i = 0; i < 8; i++)
#pragma unroll
                for (int j = 0; j < 8; j++) acc[i][j] += ra[i] * rb[j];
        }
        __syncthreads();
    }

#pragma unroll
    for (int i = 0; i < 8; i++) {
        const int r = rowBase + ty * 8 + i;
#pragma unroll
        for (int j = 0; j < 8; j += 4) {
            const int c = colBase + tx * 8 + j;
            float4 bv = *(const float4*)(bias + c);
            float4 o;
            o.x = acc[i][j + 0] + bv.x;
            o.y = acc[i][j + 1] + bv.y;
            o.z = acc[i][j + 2] + bv.z;
            o.w = acc[i][j + 3] + bv.w;
            *(float4*)(C + (size_t)r * N + c) = o;
        }
    }
}

// ---------------------------------------------------------------------------
// Logits: for each (b,h): attn[s,t] = (1/8)*dot(qp[b,s,h*64:], kp[b,t,h*64:])
//                                     + mask[b,t]*(-1e9)
// 128x128 tile over (s,t), K=64 in chunks of 16.
// ---------------------------------------------------------------------------
__global__ __launch_bounds__(256) void logits_kernel(
    const float* __restrict__ qp, const float* __restrict__ kp,
    const float* __restrict__ mask, float* __restrict__ attn)
{
    __shared__ float Qs[16][128];   // [k][s]
    __shared__ float Ks[16][128];   // [k][t]

    const int bh = blockIdx.z;
    const int b = bh >> 4;
    const int h = bh & 15;
    const int s0 = blockIdx.y * 128;
    const int t0 = blockIdx.x * 128;
    const int tid = threadIdx.x;
    const int tx = tid & 15;
    const int ty = tid >> 4;

    const float* qbase = qp + (size_t)b * SS * DD + (size_t)h * DH;
    const float* kbase = kp + (size_t)b * SS * DD + (size_t)h * DH;

    float acc[8][8];
#pragma unroll
    for (int i = 0; i < 8; i++)
#pragma unroll
        for (int j = 0; j < 8; j++) acc[i][j] = 0.f;

#pragma unroll
    for (int kk = 0; kk < DH; kk += 16) {
#pragma unroll
        for (int i = 0; i < 2; i++) {
            const int idx = tid + i * 256;      // 0..511
            const int r = idx >> 2;             // 0..127
            const int kc = (idx & 3) * 4;       // 0..12
            float4 qv = *(const float4*)(qbase + (size_t)(s0 + r) * DD + kk + kc);
            Qs[kc + 0][r] = qv.x; Qs[kc + 1][r] = qv.y;
            Qs[kc + 2][r] = qv.z; Qs[kc + 3][r] = qv.w;
            float4 kv = *(const float4*)(kbase + (size_t)(t0 + r) * DD + kk + kc);
            Ks[kc + 0][r] = kv.x; Ks[kc + 1][r] = kv.y;
            Ks[kc + 2][r] = kv.z; Ks[kc + 3][r] = kv.w;
        }
        __syncthreads();
#pragma unroll
        for (int k = 0; k < 16; k++) {
            float4 q0 = *(const float4*)&Qs[k][ty * 8];
            float4 q1 = *(const float4*)&Qs[k][ty * 8 + 4];
            float4 k0 = *(const float4*)&Ks[k][tx * 8];
            float4 k1 = *(const float4*)&Ks[k][tx * 8 + 4];
            float ra[8] = {q0.x, q0.y, q0.z, q0.w, q1.x, q1.y, q1.z, q1.w};
            float rb[8] = {k0.x, k0.y, k0.z, k0.w, k1.x, k1.y, k1.z, k1.w};
#pragma unroll
            for (int i = 0; i < 8; i++)
#pragma unroll
                for (int j = 0; j < 8; j++) acc[i][j] += ra[i] * rb[j];
        }
        __syncthreads();
    }

    const float scale = 0.125f;   // 1/sqrt(64)
    float mcol[8];
#pragma unroll
    for (int j = 0; j < 8; j++)
        mcol[j] = mask[(size_t)b * SS + t0 + tx * 8 + j] * -1e9f;

    float* obase = attn + (size_t)bh * SS * SS;
#pragma unroll
    for (int i = 0; i < 8; i++) {
        const int s = s0 + ty * 8 + i;
#pragma unroll
        for (int j = 0; j < 8; j += 4) {
            float4 o;
            o.x = acc[i][j + 0] * scale + mcol[j + 0];
            o.y = acc[i][j + 1] * scale + mcol[j + 1];
            o.z = acc[i][j + 2] * scale + mcol[j + 2];
            o.w = acc[i][j + 3] * scale + mcol[j + 3];
            *(float4*)(obase + (size_t)s * SS + t0 + tx * 8 + j) = o;
        }
    }
}

// ---------------------------------------------------------------------------
// Row softmax in place. One block per row of 2048, 256 threads, 8 elems each.
// ---------------------------------------------------------------------------
__global__ __launch_bounds__(256) void softmax_kernel(float* __restrict__ attn)
{
    const size_t row = blockIdx.x;
    float* p = attn + row * (size_t)SS;
    const int tid = threadIdx.x;

    float v[8];
    float m = -3.4e38f;
#pragma unroll
    for (int i = 0; i < 8; i++) {
        v[i] = p[tid + 256 * i];
        m = fmaxf(m, v[i]);
    }
#pragma unroll
    for (int o = 16; o; o >>= 1) m = fmaxf(m, __shfl_xor_sync(0xffffffffu, m, o));
    __shared__ float redm[8];
    if ((tid & 31) == 0) redm[tid >> 5] = m;
    __syncthreads();
    float mfull = redm[0];
#pragma unroll
    for (int i = 1; i < 8; i++) mfull = fmaxf(mfull, redm[i]);

    float sum = 0.f;
#pragma unroll
    for (int i = 0; i < 8; i++) {
        v[i] = __expf(v[i] - mfull);
        sum += v[i];
    }
#pragma unroll
    for (int o = 16; o; o >>= 1) sum += __shfl_xor_sync(0xffffffffu, sum, o);
    __shared__ float reds[8];
    if ((tid & 31) == 0) reds[tid >> 5] = sum;
    __syncthreads();
    float tot = 0.f;
#pragma unroll
    for (int i = 0; i < 8; i++) tot += reds[i];
    const float inv = 1.0f / tot;
#pragma unroll
    for (int i = 0; i < 8; i++) p[tid + 256 * i] = v[i] * inv;
}

// ---------------------------------------------------------------------------
// Context: for each (b,h): ctx[b,s,h*64+n] = sum_t attn[b,h,s,t] * vp[b,t,h*64+n]
// M=2048 (128/block), N=64 (full), K=2048 (BK=32). 256 threads, 8x4 per thread.
// ---------------------------------------------------------------------------
__global__ __launch_bounds__(256) void ctx_kernel(
    const float* __restrict__ attn, const float* __restrict__ vp,
    float* __restrict__ ctx)
{
    __shared__ float As[32][128];   // [t][s]
    __shared__ float Bs[32][64];    // [t][n]

    const int bh = blockIdx.y;
    const int b = bh >> 4;
    const int h = bh & 15;
    const int s0 = blockIdx.x * 128;
    const int tid = threadIdx.x;
    const int tx = tid & 15;        // col group of 4
    const int ty = tid >> 4;        // row group of 8

    const float* abase = attn + (size_t)bh * SS * SS;
    const float* vbase = vp + (size_t)b * SS * DD + (size_t)h * DH;

    float acc[8][4];
#pragma unroll
    for (int i = 0; i < 8; i++)
#pragma unroll
        for (int j = 0; j < 4; j++) acc[i][j] = 0.f;

    for (int kt = 0; kt < SS; kt += 32) {
#pragma unroll
        for (int i = 0; i < 4; i++) {
            const int idx = tid + i * 256;   // 0..1023
            const int r = idx >> 3;          // 0..127
            const int tc = (idx & 7) * 4;    // 0..28
            float4 av = *(const float4*)(abase + (size_t)(s0 + r) * SS + kt + tc);
            As[tc + 0][r] = av.x; As[tc + 1][r] = av.y;
            As[tc + 2][r] = av.z; As[tc + 3][r] = av.w;
        }
#pragma unroll
        for (int i = 0; i < 2; i++) {
            const int idx = tid + i * 256;   // 0..511
            const int tr = idx >> 4;         // 0..31
            const int nc = (idx & 15) * 4;   // 0..60
            *(float4*)&Bs[tr][nc] =
                *(const float4*)(vbase + (size_t)(kt + tr) * DD + nc);
        }
        __syncthreads();
#pragma unroll
        for (int k = 0; k < 32; k++) {
            float4 a0 = *(const float4*)&As[k][ty * 8];
            float4 a1 = *(const float4*)&As[k][ty * 8 + 4];
            float4 bv = *(const float4*)&Bs[k][tx * 4];
            float ra[8] = {a0.x, a0.y, a0.z, a0.w, a1.x, a1.y, a1.z, a1.w};
            float rb[4] = {bv.x, bv.y, bv.z, bv.w};
#pragma unroll
            for (int i = 0; i < 8; i++)
#pragma unroll
                for (int j = 0; j < 4; j++) acc[i][j] += ra[i] * rb[j];
        }
        __syncthreads();
    }

    float* obase = ctx + (size_t)b * SS * DD + (size_t)h * DH;
#pragma unroll
    for (int i = 0; i < 8; i++) {
        const int s = s0 + ty * 8 + i;
        float4 o;
        o.x = acc[i][0]; o.y = acc[i][1]; o.z = acc[i][2]; o.w = acc[i][3];
        *(float4*)(obase + (size_t)s * DD + tx * 4) = o;
    }
}

// ---------------------------------------------------------------------------
extern "C" void kernel_launch(void* const* d_in, const int* in_sizes, int n_in,
                              void* d_out, int out_size)
{
    const float* q    = (const float*)d_in[0];
    const float* k    = (const float*)d_in[1];
    const float* v    = (const float*)d_in[2];
    const float* mask = (const float*)d_in[3];
    const float* wq   = (const float*)d_in[4];
    const float* bq   = (const float*)d_in[5];
    const float* wk   = (const float*)d_in[6];
    const float* bk   = (const float*)d_in[7];
    const float* wv   = (const float*)d_in[8];
    const float* bv   = (const float*)d_in[9];
    const float* wo   = (const float*)d_in[10];
    const float* bo   = (const float*)d_in[11];
    float* out = (float*)d_out;

    float *qp, *kp, *vp, *ctx, *attn;
    cudaGetSymbolAddress((void**)&qp,  g_qp);
    cudaGetSymbolAddress((void**)&kp,  g_kp);
    cudaGetSymbolAddress((void**)&vp,  g_vp);
    cudaGetSymbolAddress((void**)&ctx, g_ctx);
    if ((size_t)out_size >= OUT_ELEMS + ATTN_ELEMS) {
        attn = out + OUT_ELEMS;     // harness output holds (out, attn)
    } else {
        cudaGetSymbolAddress((void**)&attn, g_attn_fb);
    }

    dim3 gproj(DD / 128, MROWS / 128);          // (8, 32)
    sgemm_bias_kernel<<<gproj, 256>>>(q, wq, bq, qp, MROWS, DD, DD);
    sgemm_bias_kernel<<<gproj, 256>>>(k, wk, bk, kp, MROWS, DD, DD);
    sgemm_bias_kernel<<<gproj, 256>>>(v, wv, bv, vp, MROWS, DD, DD);

    logits_kernel<<<dim3(SS / 128, SS / 128, BB * HH), 256>>>(qp, kp, mask, attn);
    softmax_kernel<<<(unsigned)(BB * HH * SS), 256>>>(attn);
    ctx_kernel<<<dim3(SS / 128, BB * HH), 256>>>(attn, vp, ctx);

    sgemm_bias_kernel<<<gproj, 256>>>(ctx, wo, bo, out, MROWS, DD, DD);
}

// round 2
// speedup vs baseline: 2.2673x; 2.2673x over previous
#include <cuda_runtime.h>
#include <stdint.h>
#include <math.h>

#define BB 2
#define HH 16
#define SS 2048
#define DD 1024
#define DH 64
#define MROWS (BB*SS)   // 4096

static const size_t OUT_ELEMS  = (size_t)BB * SS * DD;            // 4,194,304
static const size_t ATTN_ELEMS = (size_t)BB * HH * SS * SS;       // 134,217,728

// Scratch (__device__ globals; allocation in kernel_launch is forbidden)
__device__ float g_qp[MROWS * DD];
__device__ float g_kp[MROWS * DD];
__device__ float g_vp[MROWS * DD];
__device__ float g_ctx[MROWS * DD];
__device__ float g_attn_fb[(size_t)BB * HH * SS * SS];

// ---------------------------------------------------------------------------
// TF32 helpers
// ---------------------------------------------------------------------------
__device__ __forceinline__ uint32_t f2tf(float f) {
    uint32_t u;
    asm("cvt.rna.tf32.f32 %0, %1;" : "=r"(u) : "f"(f));
    return u;
}

__device__ __forceinline__ void mma_tf32(float c[4], const uint32_t a[4],
                                         const uint32_t b[2]) {
    asm volatile(
        "mma.sync.aligned.m16n8k8.row.col.f32.tf32.tf32.f32 "
        "{%0,%1,%2,%3}, {%4,%5,%6,%7}, {%8,%9}, {%0,%1,%2,%3};\n"
        : "+f"(c[0]), "+f"(c[1]), "+f"(c[2]), "+f"(c[3])
        : "r"(a[0]), "r"(a[1]), "r"(a[2]), "r"(a[3]), "r"(b[0]), "r"(b[1]));
}

// ---------------------------------------------------------------------------
// SGEMM + bias on tensor cores: C[M,N] = A[M,K] @ W[K,N] + bias[N]
// Block 128x128, BK=32, 256 threads = 8 warps (2m x 4n), warp tile 64x32.
// ---------------------------------------------------------------------------
__global__ __launch_bounds__(256, 2) void sgemm_bias_tc(
    const float* __restrict__ A, const float* __restrict__ W,
    const float* __restrict__ bias, float* __restrict__ C,
    int M, int N, int K)
{
    __shared__ uint32_t As[128][36];   // [m][k], pad 36 -> frag bank = g*4+t4
    __shared__ uint32_t Bs[32][136];   // [k][n], pad 136 -> frag bank = t4*8+g

    const int tid = threadIdx.x;
    const int lane = tid & 31;
    const int warp = tid >> 5;
    const int g = lane >> 2;       // groupID 0..7
    const int t4 = lane & 3;       // threadID_in_group 0..3
    const int warpM = warp >> 2;   // 0..1
    const int warpN = warp & 3;    // 0..3
    const int rowBase = blockIdx.y * 128;
    const int colBase = blockIdx.x * 128;
    const int mOff = warpM * 64;
    const int nOff = warpN * 32;

    float acc[4][4][4];
#pragma unroll
    for (int m = 0; m < 4; m++)
#pragma unroll
        for (int n = 0; n < 4; n++)
#pragma unroll
            for (int i = 0; i < 4; i++) acc[m][n][i] = 0.f;

    for (int k0 = 0; k0 < K; k0 += 32) {
        // A tile: 128 rows x 32 k = 1024 float4; 4 per thread
#pragma unroll
        for (int i = 0; i < 4; i++) {
            int l = tid + i * 256;
            int r = l >> 3, kc = (l & 7) * 4;
            float4 v = *(const float4*)(A + (size_t)(rowBase + r) * K + k0 + kc);
            uint4 u;
            u.x = f2tf(v.x); u.y = f2tf(v.y); u.z = f2tf(v.z); u.w = f2tf(v.w);
            *(uint4*)&As[r][kc] = u;
        }
        // W tile: 32 rows x 128 n = 1024 float4; 4 per thread
#pragma unroll
        for (int i = 0; i < 4; i++) {
            int l = tid + i * 256;
            int r = l >> 5, nc = (l & 31) * 4;
            float4 v = *(const float4*)(W + (size_t)(k0 + r) * N + colBase + nc);
            uint4 u;
            u.x = f2tf(v.x); u.y = f2tf(v.y); u.z = f2tf(v.z); u.w = f2tf(v.w);
            *(uint4*)&Bs[r][nc] = u;
        }
        __syncthreads();

#pragma unroll
        for (int kk = 0; kk < 32; kk += 8) {
            uint32_t af[4][4], bf[4][2];
#pragma unroll
            for (int m = 0; m < 4; m++) {
                int mr = mOff + m * 16 + g;
                af[m][0] = As[mr][kk + t4];
                af[m][1] = As[mr + 8][kk + t4];
                af[m][2] = As[mr][kk + t4 + 4];
                af[m][3] = As[mr + 8][kk + t4 + 4];
            }
#pragma unroll
            for (int n = 0; n < 4; n++) {
                int nc = nOff + n * 8 + g;
                bf[n][0] = Bs[kk + t4][nc];
                bf[n][1] = Bs[kk + t4 + 4][nc];
            }
#pragma unroll
            for (int m = 0; m < 4; m++)
#pragma unroll
                for (int n = 0; n < 4; n++) mma_tf32(acc[m][n], af[m], bf[n]);
        }
        __syncthreads();
    }

#pragma unroll
    for (int m = 0; m < 4; m++) {
        int r0 = rowBase + mOff + m * 16 + g;
#pragma unroll
        for (int n = 0; n < 4; n++) {
            int c0 = colBase + nOff + n * 8 + t4 * 2;
            float2 bv = *(const float2*)(bias + c0);
            float2 o0, o1;
            o0.x = acc[m][n][0] + bv.x; o0.y = acc[m][n][1] + bv.y;
            o1.x = acc[m][n][2] + bv.x; o1.y = acc[m][n][3] + bv.y;
            *(float2*)(C + (size_t)r0 * N + c0) = o0;
            *(float2*)(C + (size_t)(r0 + 8) * N + c0) = o1;
        }
    }
}

// ---------------------------------------------------------------------------
// Logits on tensor cores: attn[b,h,s,t] = 0.125 * <q[s,:], k[t,:]> + mask*-1e9
// Block 128(s) x 128(t), K=64 in two BK=32 steps. Q,K both stored [row][d].
// ---------------------------------------------------------------------------
__global__ __launch_bounds__(256, 2) void logits_tc(
    const float* __restrict__ qp, const float* __restrict__ kp,
    const float* __restrict__ mask, float* __restrict__ attn)
{
    __shared__ uint32_t Qs[128][36];
    __shared__ uint32_t Ks[128][36];

    const int tid = threadIdx.x;
    const int lane = tid & 31;
    const int warp = tid >> 5;
    const int g = lane >> 2, t4 = lane & 3;
    const int warpM = warp >> 2, warpN = warp & 3;
    const int bh = blockIdx.z, b = bh >> 4, h = bh & 15;
    const int s0 = blockIdx.y * 128, t0 = blockIdx.x * 128;

    const float* qb = qp + (size_t)b * SS * DD + (size_t)h * DH;
    const float* kb = kp + (size_t)b * SS * DD + (size_t)h * DH;

    float acc[4][4][4];
#pragma unroll
    for (int m = 0; m < 4; m++)
#pragma unroll
        for (int n = 0; n < 4; n++)
#pragma unroll
            for (int i = 0; i < 4; i++) acc[m][n][i] = 0.f;

#pragma unroll
    for (int kt = 0; kt < DH; kt += 32) {
#pragma unroll
        for (int i = 0; i < 4; i++) {
            int l = tid + i * 256;
            int r = l >> 3, dc = (l & 7) * 4;
            float4 v = *(const float4*)(qb + (size_t)(s0 + r) * DD + kt + dc);
            uint4 u;
            u.x = f2tf(v.x); u.y = f2tf(v.y); u.z = f2tf(v.z); u.w = f2tf(v.w);
            *(uint4*)&Qs[r][dc] = u;
            float4 w = *(const float4*)(kb + (size_t)(t0 + r) * DD + kt + dc);
            uint4 u2;
            u2.x = f2tf(w.x); u2.y = f2tf(w.y); u2.z = f2tf(w.z); u2.w = f2tf(w.w);
            *(uint4*)&Ks[r][dc] = u2;
        }
        __syncthreads();

#pragma unroll
        for (int kk = 0; kk < 32; kk += 8) {
            uint32_t af[4][4], bf[4][2];
#pragma unroll
            for (int m = 0; m < 4; m++) {
                int mr = warpM * 64 + m * 16 + g;
                af[m][0] = Qs[mr][kk + t4];
                af[m][1] = Qs[mr + 8][kk + t4];
                af[m][2] = Qs[mr][kk + t4 + 4];
                af[m][3] = Qs[mr + 8][kk + t4 + 4];
            }
#pragma unroll
            for (int n = 0; n < 4; n++) {
                int nr = warpN * 32 + n * 8 + g;   // B[k][n] = K[t=n][d=k]
                bf[n][0] = Ks[nr][kk + t4];
                bf[n][1] = Ks[nr][kk + t4 + 4];
            }
#pragma unroll
            for (int m = 0; m < 4; m++)
#pragma unroll
                for (int n = 0; n < 4; n++) mma_tf32(acc[m][n], af[m], bf[n]);
        }
        __syncthreads();
    }

    float* ob = attn + (size_t)bh * SS * SS;
#pragma unroll
    for (int m = 0; m < 4; m++) {
        int r0 = s0 + warpM * 64 + m * 16 + g;
#pragma unroll
        for (int n = 0; n < 4; n++) {
            int c0 = t0 + warpN * 32 + n * 8 + t4 * 2;
            float2 mv = *(const float2*)(mask + (size_t)b * SS + c0);
            float m0 = mv.x * -1e9f, m1 = mv.y * -1e9f;
            float2 o0, o1;
            o0.x = acc[m][n][0] * 0.125f + m0;
            o0.y = acc[m][n][1] * 0.125f + m1;
            o1.x = acc[m][n][2] * 0.125f + m0;
            o1.y = acc[m][n][3] * 0.125f + m1;
            *(float2*)(ob + (size_t)r0 * SS + c0) = o0;
            *(float2*)(ob + (size_t)(r0 + 8) * SS + c0) = o1;
        }
    }
}

// ---------------------------------------------------------------------------
// Row softmax in place, 1 block per row of 2048, 256 threads.
// ---------------------------------------------------------------------------
__global__ __launch_bounds__(256) void softmax_kernel(float* __restrict__ attn)
{
    const size_t row = blockIdx.x;
    float* p = attn + row * (size_t)SS;
    const int tid = threadIdx.x;

    float v[8];
    float m = -3.4e38f;
#pragma unroll
    for (int i = 0; i < 8; i++) {
        v[i] = p[tid + 256 * i];
        m = fmaxf(m, v[i]);
    }
#pragma unroll
    for (int o = 16; o; o >>= 1) m = fmaxf(m, __shfl_xor_sync(0xffffffffu, m, o));
    __shared__ float redm[8];
    if ((tid & 31) == 0) redm[tid >> 5] = m;
    __syncthreads();
    float mfull = redm[0];
#pragma unroll
    for (int i = 1; i < 8; i++) mfull = fmaxf(mfull, redm[i]);

    float sum = 0.f;
#pragma unroll
    for (int i = 0; i < 8; i++) {
        v[i] = __expf(v[i] - mfull);
        sum += v[i];
    }
#pragma unroll
    for (int o = 16; o; o >>= 1) sum += __shfl_xor_sync(0xffffffffu, sum, o);
    __shared__ float reds[8];
    if ((tid & 31) == 0) reds[tid >> 5] = sum;
    __syncthreads();
    float tot = 0.f;
#pragma unroll
    for (int i = 0; i < 8; i++) tot += reds[i];
    const float inv = 1.0f / tot;
#pragma unroll
    for (int i = 0; i < 8; i++) p[tid + 256 * i] = v[i] * inv;
}

// ---------------------------------------------------------------------------
// Context on tensor cores: ctx[b,s,h*64+n] = sum_t attn[b,h,s,t]*vp[b,t,h*64+n]
// Block 128(m) x 64(n), BK=32, 8 warps (4m x 2n), warp tile 32x32.
// ---------------------------------------------------------------------------
__global__ __launch_bounds__(256, 2) void ctx_tc(
    const float* __restrict__ attn, const float* __restrict__ vp,
    float* __restrict__ ctx)
{
    __shared__ uint32_t As[128][36];   // attn tile [s][t]
    __shared__ uint32_t Vs[32][72];    // v tile [t][n], pad 72

    const int tid = threadIdx.x;
    const int lane = tid & 31;
    const int warp = tid >> 5;
    const int g = lane >> 2, t4 = lane & 3;
    const int warpM = warp >> 1;   // 0..3
    const int warpN = warp & 1;    // 0..1
    const int bh = blockIdx.y, b = bh >> 4, h = bh & 15;
    const int s0 = blockIdx.x * 128;

    const float* ab = attn + (size_t)bh * SS * SS;
    const float* vb = vp + (size_t)b * SS * DD + (size_t)h * DH;

    float acc[2][4][4];
#pragma unroll
    for (int m = 0; m < 2; m++)
#pragma unroll
        for (int n = 0; n < 4; n++)
#pragma unroll
            for (int i = 0; i < 4; i++) acc[m][n][i] = 0.f;

    for (int kt = 0; kt < SS; kt += 32) {
#pragma unroll
        for (int i = 0; i < 4; i++) {
            int l = tid + i * 256;
            int r = l >> 3, tc = (l & 7) * 4;
            float4 v = *(const float4*)(ab + (size_t)(s0 + r) * SS + kt + tc);
            uint4 u;
            u.x = f2tf(v.x); u.y = f2tf(v.y); u.z = f2tf(v.z); u.w = f2tf(v.w);
            *(uint4*)&As[r][tc] = u;
        }
#pragma unroll
        for (int i = 0; i < 2; i++) {
            int l = tid + i * 256;
            int r = l >> 4, nc = (l & 15) * 4;
            float4 v = *(const float4*)(vb + (size_t)(kt + r) * DD + nc);
            uint4 u;
            u.x = f2tf(v.x); u.y = f2tf(v.y); u.z = f2tf(v.z); u.w = f2tf(v.w);
            *(uint4*)&Vs[r][nc] = u;
        }
        __syncthreads();

#pragma unroll
        for (int kk = 0; kk < 32; kk += 8) {
            uint32_t af[2][4], bf[4][2];
#pragma unroll
            for (int m = 0; m < 2; m++) {
                int mr = warpM * 32 + m * 16 + g;
                af[m][0] = As[mr][kk + t4];
                af[m][1] = As[mr + 8][kk + t4];
                af[m][2] = As[mr][kk + t4 + 4];
                af[m][3] = As[mr + 8][kk + t4 + 4];
            }
#pragma unroll
            for (int n = 0; n < 4; n++) {
                int nc = warpN * 32 + n * 8 + g;
                bf[n][0] = Vs[kk + t4][nc];
                bf[n][1] = Vs[kk + t4 + 4][nc];
            }
#pragma unroll
            for (int m = 0; m < 2; m++)
#pragma unroll
                for (int n = 0; n < 4; n++) mma_tf32(acc[m][n], af[m], bf[n]);
        }
        __syncthreads();
    }

#pragma unroll
    for (int m = 0; m < 2; m++) {
        int r0 = s0 + warpM * 32 + m * 16 + g;
#pragma unroll
        for (int n = 0; n < 4; n++) {
            int c0 = warpN * 32 + n * 8 + t4 * 2;
            float2 o0, o1;
            o0.x = acc[m][n][0]; o0.y = acc[m][n][1];
            o1.x = acc[m][n][2]; o1.y = acc[m][n][3];
            *(float2*)(ctx + ((size_t)b * SS + r0) * DD + h * DH + c0) = o0;
            *(float2*)(ctx + ((size_t)b * SS + r0 + 8) * DD + h * DH + c0) = o1;
        }
    }
}

// ---------------------------------------------------------------------------
extern "C" void kernel_launch(void* const* d_in, const int* in_sizes, int n_in,
                              void* d_out, int out_size)
{
    const float* q    = (const float*)d_in[0];
    const float* k    = (const float*)d_in[1];
    const float* v    = (const float*)d_in[2];
    const float* mask = (const float*)d_in[3];
    const float* wq   = (const float*)d_in[4];
    const float* bq   = (const float*)d_in[5];
    const float* wk   = (const float*)d_in[6];
    const float* bk   = (const float*)d_in[7];
    const float* wv   = (const float*)d_in[8];
    const float* bv   = (const float*)d_in[9];
    const float* wo   = (const float*)d_in[10];
    const float* bo   = (const float*)d_in[11];
    float* out = (float*)d_out;

    float *qp, *kp, *vp, *ctx, *attn;
    cudaGetSymbolAddress((void**)&qp,  g_qp);
    cudaGetSymbolAddress((void**)&kp,  g_kp);
    cudaGetSymbolAddress((void**)&vp,  g_vp);
    cudaGetSymbolAddress((void**)&ctx, g_ctx);
    if ((size_t)out_size >= OUT_ELEMS + ATTN_ELEMS) {
        attn = out + OUT_ELEMS;
    } else {
        cudaGetSymbolAddress((void**)&attn, g_attn_fb);
    }

    dim3 gproj(DD / 128, MROWS / 128);          // (8, 32)
    sgemm_bias_tc<<<gproj, 256>>>(q, wq, bq, qp, MROWS, DD, DD);
    sgemm_bias_tc<<<gproj, 256>>>(k, wk, bk, kp, MROWS, DD, DD);
    sgemm_bias_tc<<<gproj, 256>>>(v, wv, bv, vp, MROWS, DD, DD);

    logits_tc<<<dim3(SS / 128, SS / 128, BB * HH), 256>>>(qp, kp, mask, attn);
    softmax_kernel<<<(unsigned)(BB * HH * SS), 256>>>(attn);
    ctx_tc<<<dim3(SS / 128, BB * HH), 256>>>(attn, vp, ctx);

    sgemm_bias_tc<<<gproj, 256>>>(ctx, wo, bo, out, MROWS, DD, DD);
}